// round 2
// baseline (speedup 1.0000x reference)
#include <cuda_runtime.h>
#include <math.h>

// ChamferLoss: predict_pc (4,3,4096), gt_pc (4,3,4096) -> scalar
// out = mean_m sqrt(min_n ||p_m - g_n||^2 + 1e-8) + mean_n sqrt(min_m ||p_m - g_n||^2 + 1e-8)

#define BATCH 4
#define NPTS  4096
#define THREADS 256
#define TILES (NPTS / THREADS)   // 16 tiles of 256 query points

__global__ void chamfer_zero_kernel(float* out) {
    if (threadIdx.x == 0) out[0] = 0.0f;
}

__global__ __launch_bounds__(THREADS)
void ChamferLoss_42898133352708_kernel(const float* __restrict__ predict,
                                       const float* __restrict__ gt,
                                       float* __restrict__ out) {
    const int b    = blockIdx.z;          // batch
    const int dir  = blockIdx.y;          // 0: query=predict, db=gt ; 1: swapped
    const int tile = blockIdx.x;
    const int tid  = threadIdx.x;

    const float* q  = (dir == 0) ? predict : gt;   // query side
    const float* db = (dir == 0) ? gt : predict;   // database side

    const int base = b * 3 * NPTS;

    // Cache full database point cloud in shared: 3 * 4096 * 4B = 48 KB
    __shared__ float sx[NPTS];
    __shared__ float sy[NPTS];
    __shared__ float sz[NPTS];

    #pragma unroll
    for (int i = tid; i < NPTS; i += THREADS) {
        sx[i] = db[base + 0 * NPTS + i];
        sy[i] = db[base + 1 * NPTS + i];
        sz[i] = db[base + 2 * NPTS + i];
    }
    __syncthreads();

    const int m = tile * THREADS + tid;
    const float px = q[base + 0 * NPTS + m];
    const float py = q[base + 1 * NPTS + m];
    const float pz = q[base + 2 * NPTS + m];

    // 4 independent min accumulators to break the FMNMX dependence chain
    float mn0 = 3.4e38f, mn1 = 3.4e38f, mn2 = 3.4e38f, mn3 = 3.4e38f;

    #pragma unroll 4
    for (int n = 0; n < NPTS; n += 4) {
        {
            float dx = px - sx[n + 0];
            float dy = py - sy[n + 0];
            float dz = pz - sz[n + 0];
            float d  = fmaf(dx, dx, fmaf(dy, dy, dz * dz));
            mn0 = fminf(mn0, d);
        }
        {
            float dx = px - sx[n + 1];
            float dy = py - sy[n + 1];
            float dz = pz - sz[n + 1];
            float d  = fmaf(dx, dx, fmaf(dy, dy, dz * dz));
            mn1 = fminf(mn1, d);
        }
        {
            float dx = px - sx[n + 2];
            float dy = py - sy[n + 2];
            float dz = pz - sz[n + 2];
            float d  = fmaf(dx, dx, fmaf(dy, dy, dz * dz));
            mn2 = fminf(mn2, d);
        }
        {
            float dx = px - sx[n + 3];
            float dy = py - sy[n + 3];
            float dz = pz - sz[n + 3];
            float d  = fmaf(dx, dx, fmaf(dy, dy, dz * dz));
            mn3 = fminf(mn3, d);
        }
    }

    float mn = fminf(fminf(mn0, mn1), fminf(mn2, mn3));

    // mean over B*NPTS points per direction (both directions have 16384 terms)
    float val = sqrtf(mn + 1e-8f) * (1.0f / (float)(BATCH * NPTS));

    // Block reduction, then one atomicAdd per block
    __shared__ float red[THREADS];
    red[tid] = val;
    __syncthreads();
    #pragma unroll
    for (int s = THREADS / 2; s >= 32; s >>= 1) {
        if (tid < s) red[tid] += red[tid + s];
        __syncthreads();
    }
    if (tid < 32) {
        float v = red[tid];
        #pragma unroll
        for (int off = 16; off > 0; off >>= 1)
            v += __shfl_down_sync(0xFFFFFFFFu, v, off);
        if (tid == 0) atomicAdd(out, v);
    }
}

extern "C" void kernel_launch(void* const* d_in, const int* in_sizes, int n_in,
                              void* d_out, int out_size) {
    const float* predict = (const float*)d_in[0];
    const float* gt      = (const float*)d_in[1];
    float* out = (float*)d_out;

    chamfer_zero_kernel<<<1, 32>>>(out);

    dim3 grid(TILES, 2, BATCH);   // 16 x 2 x 4 = 128 blocks
    ChamferLoss_42898133352708_kernel<<<grid, THREADS>>>(predict, gt, out);
}

// round 3
// speedup vs baseline: 1.2595x; 1.2595x over previous
#include <cuda_runtime.h>
#include <math.h>

// ChamferLoss: predict_pc (4,3,4096), gt_pc (4,3,4096) -> scalar
// out = mean_m sqrt(min_n ||p_m-g_n||^2 + 1e-8) + mean_n sqrt(min_m ... )
//
// Strategy: min_n ||p-g||^2 = |p|^2 + 2*min_n( h_n - p.g_n ),  h_n = 0.5|g_n|^2
// Inner loop: packed f32x2 FFMA over database point-pairs stored interleaved
// in shared as {x0,x1, y0,y1, z0,z1, h0,h1} (32B records, 2x LDS.128 each).

#define BATCH   4
#define NPTS    4096
#define THREADS 256
#define TILES   (NPTS / THREADS)      // 16
#define CHUNK   2048                  // db points per shared chunk (32 KB)
#define PAIRS   (CHUNK / 2)           // 1024 point-pairs per chunk

__device__ __forceinline__ unsigned long long pack2(float lo, float hi) {
    unsigned long long r;
    asm("mov.b64 %0, {%1, %2};" : "=l"(r) : "f"(lo), "f"(hi));
    return r;
}
__device__ __forceinline__ void unpack2(unsigned long long v, float& lo, float& hi) {
    asm("mov.b64 {%0, %1}, %2;" : "=f"(lo), "=f"(hi) : "l"(v));
}
__device__ __forceinline__ unsigned long long fma2(unsigned long long a,
                                                   unsigned long long b,
                                                   unsigned long long c) {
    unsigned long long d;
    asm("fma.rn.f32x2 %0, %1, %2, %3;" : "=l"(d) : "l"(a), "l"(b), "l"(c));
    return d;
}

__global__ void chamfer_zero_kernel(float* out) {
    if (threadIdx.x == 0) out[0] = 0.0f;
}

__global__ __launch_bounds__(THREADS)
void ChamferLoss_42898133352708_kernel(const float* __restrict__ predict,
                                       const float* __restrict__ gt,
                                       float* __restrict__ out) {
    const int b    = blockIdx.z;
    const int dir  = blockIdx.y;          // 0: query=predict db=gt ; 1: swapped
    const int tile = blockIdx.x;
    const int tid  = threadIdx.x;

    const float* q  = (dir == 0) ? predict : gt;
    const float* db = (dir == 0) ? gt : predict;
    const int base  = b * 3 * NPTS;

    // Interleaved pair records: rec[j] = {x0,x1, y0,y1, z0,z1, h0,h1}
    __shared__ float sdb[CHUNK * 4];      // 32 KB

    // Query point (negated for score = h - p.g via fma)
    const int m = tile * THREADS + tid;
    const float px = q[base + 0 * NPTS + m];
    const float py = q[base + 1 * NPTS + m];
    const float pz = q[base + 2 * NPTS + m];
    const unsigned long long qx2 = pack2(-px, -px);
    const unsigned long long qy2 = pack2(-py, -py);
    const unsigned long long qz2 = pack2(-pz, -pz);
    const float pp = fmaf(px, px, fmaf(py, py, pz * pz));

    float mn0 = 3.4e38f, mn1 = 3.4e38f, mn2 = 3.4e38f, mn3 = 3.4e38f;

    #pragma unroll
    for (int c = 0; c < NPTS / CHUNK; ++c) {
        // Load chunk: 8 db points per thread, compute h on the fly
        #pragma unroll
        for (int k = tid; k < CHUNK; k += THREADS) {
            const int i = c * CHUNK + k;
            const float gx = db[base + 0 * NPTS + i];
            const float gy = db[base + 1 * NPTS + i];
            const float gz = db[base + 2 * NPTS + i];
            const float h  = 0.5f * fmaf(gx, gx, fmaf(gy, gy, gz * gz));
            const int j = k >> 1, lane = k & 1;
            sdb[j * 8 + 0 + lane] = gx;
            sdb[j * 8 + 2 + lane] = gy;
            sdb[j * 8 + 4 + lane] = gz;
            sdb[j * 8 + 6 + lane] = h;
        }
        __syncthreads();

        const ulonglong2* s2 = (const ulonglong2*)sdb;

        // 2 point-pairs (4 db points) per iteration, 4 min accumulators
        #pragma unroll 2
        for (int j = 0; j < PAIRS; j += 2) {
            const ulonglong2 A0 = s2[2 * j + 0];   // {x0,x1},{y0,y1}
            const ulonglong2 B0 = s2[2 * j + 1];   // {z0,z1},{h0,h1}
            const ulonglong2 A1 = s2[2 * j + 2];
            const ulonglong2 B1 = s2[2 * j + 3];

            unsigned long long sc0 = fma2(qx2, A0.x, fma2(qy2, A0.y, fma2(qz2, B0.x, B0.y)));
            unsigned long long sc1 = fma2(qx2, A1.x, fma2(qy2, A1.y, fma2(qz2, B1.x, B1.y)));

            float a, bb, cc, dd;
            unpack2(sc0, a, bb);
            unpack2(sc1, cc, dd);
            mn0 = fminf(mn0, a);
            mn1 = fminf(mn1, bb);
            mn2 = fminf(mn2, cc);
            mn3 = fminf(mn3, dd);
        }
        __syncthreads();
    }

    const float mnsc = fminf(fminf(mn0, mn1), fminf(mn2, mn3));
    // d2_min = pp + 2*score_min  (clamp tiny negative from cancellation)
    const float d2 = fmaxf(fmaf(2.0f, mnsc, pp), 0.0f);
    const float val = sqrtf(d2 + 1e-8f) * (1.0f / (float)(BATCH * NPTS));

    // Block reduction + one atomic per block
    __shared__ float red[THREADS];
    red[tid] = val;
    __syncthreads();
    #pragma unroll
    for (int s = THREADS / 2; s >= 32; s >>= 1) {
        if (tid < s) red[tid] += red[tid + s];
        __syncthreads();
    }
    if (tid < 32) {
        float v = red[tid];
        #pragma unroll
        for (int off = 16; off > 0; off >>= 1)
            v += __shfl_down_sync(0xFFFFFFFFu, v, off);
        if (tid == 0) atomicAdd(out, v);
    }
}

extern "C" void kernel_launch(void* const* d_in, const int* in_sizes, int n_in,
                              void* d_out, int out_size) {
    const float* predict = (const float*)d_in[0];
    const float* gt      = (const float*)d_in[1];
    float* out = (float*)d_out;

    chamfer_zero_kernel<<<1, 32>>>(out);

    dim3 grid(TILES, 2, BATCH);   // 16 x 2 x 4 = 128 blocks
    ChamferLoss_42898133352708_kernel<<<grid, THREADS>>>(predict, gt, out);
}

// round 4
// speedup vs baseline: 1.5088x; 1.1980x over previous
#include <cuda_runtime.h>
#include <math.h>

// ChamferLoss: predict_pc (4,3,4096), gt_pc (4,3,4096) -> scalar
// min_n ||p-g||^2 = |p|^2 + 2*min_n( h_n - p.g_n ),  h_n = 0.5|g_n|^2
// Stage A: 128 blocks, each = (query tile of 1024, db quarter of 1024 pts).
//          4 queries/thread share each shared-memory record (amortize LDS).
//          Packed f32x2 FFMA covers 2 db points per op.
// Stage B: combine 4 quarter-mins per query, sqrt, mean, atomicAdd.

#define BATCH   4
#define NPTS    4096
#define THREADS 256
#define QPT     4                       // queries per thread
#define DBQ     1024                    // db points per quarter
#define RECS    (DBQ / 2)               // 512 interleaved 2-point records

// scratch[dir][b][quarter][query] : 2*4*4*4096 floats = 512 KB
__device__ float g_scratch[2 * 4 * 4 * 4096];

__device__ __forceinline__ unsigned long long pack2(float lo, float hi) {
    unsigned long long r;
    asm("mov.b64 %0, {%1, %2};" : "=l"(r) : "f"(lo), "f"(hi));
    return r;
}
__device__ __forceinline__ void unpack2(unsigned long long v, float& lo, float& hi) {
    asm("mov.b64 {%0, %1}, %2;" : "=f"(lo), "=f"(hi) : "l"(v));
}
__device__ __forceinline__ unsigned long long fma2(unsigned long long a,
                                                   unsigned long long b,
                                                   unsigned long long c) {
    unsigned long long d;
    asm("fma.rn.f32x2 %0, %1, %2, %3;" : "=l"(d) : "l"(a), "l"(b), "l"(c));
    return d;
}

__global__ void chamfer_zero_kernel(float* out) {
    if (threadIdx.x == 0) out[0] = 0.0f;
}

__global__ __launch_bounds__(THREADS)
void chamfer_stageA(const float* __restrict__ predict,
                    const float* __restrict__ gt) {
    const int tile    = blockIdx.x >> 2;   // 0..3  (query tile of 1024)
    const int quarter = blockIdx.x & 3;    // 0..3  (db quarter of 1024)
    const int dir     = blockIdx.y;        // 0: q=predict db=gt ; 1: swapped
    const int b       = blockIdx.z;
    const int tid     = threadIdx.x;

    const float* q  = (dir == 0) ? predict : gt;
    const float* db = (dir == 0) ? gt : predict;
    const int base  = b * 3 * NPTS;

    // Interleaved records: rec[j] = {x0,x1, y0,y1, z0,z1, h0,h1}  (16 KB)
    __shared__ float sdb[DBQ * 4];

    #pragma unroll
    for (int k = tid; k < DBQ; k += THREADS) {
        const int i  = quarter * DBQ + k;
        const float gx = db[base + 0 * NPTS + i];
        const float gy = db[base + 1 * NPTS + i];
        const float gz = db[base + 2 * NPTS + i];
        const float h  = 0.5f * fmaf(gx, gx, fmaf(gy, gy, gz * gz));
        const int j = k >> 1, lane = k & 1;
        sdb[j * 8 + 0 + lane] = gx;
        sdb[j * 8 + 2 + lane] = gy;
        sdb[j * 8 + 4 + lane] = gz;
        sdb[j * 8 + 6 + lane] = h;
    }
    __syncthreads();

    // 4 query points per thread (negated coords so score = h - p.g via fma)
    unsigned long long qx2[QPT], qy2[QPT], qz2[QPT];
    const int qbase = tile * (THREADS * QPT) + tid;
    #pragma unroll
    for (int jq = 0; jq < QPT; ++jq) {
        const int m = qbase + jq * THREADS;
        const float px = q[base + 0 * NPTS + m];
        const float py = q[base + 1 * NPTS + m];
        const float pz = q[base + 2 * NPTS + m];
        qx2[jq] = pack2(-px, -px);
        qy2[jq] = pack2(-py, -py);
        qz2[jq] = pack2(-pz, -pz);
    }

    float mnA[QPT], mnB[QPT];
    #pragma unroll
    for (int jq = 0; jq < QPT; ++jq) { mnA[jq] = 3.4e38f; mnB[jq] = 3.4e38f; }

    const ulonglong2* s2 = (const ulonglong2*)sdb;
    #pragma unroll 2
    for (int r = 0; r < RECS; ++r) {
        const ulonglong2 A = s2[2 * r + 0];   // {x0,x1},{y0,y1}
        const ulonglong2 B = s2[2 * r + 1];   // {z0,z1},{h0,h1}
        #pragma unroll
        for (int jq = 0; jq < QPT; ++jq) {
            const unsigned long long sc =
                fma2(qx2[jq], A.x, fma2(qy2[jq], A.y, fma2(qz2[jq], B.x, B.y)));
            float lo, hi;
            unpack2(sc, lo, hi);
            mnA[jq] = fminf(mnA[jq], lo);
            mnB[jq] = fminf(mnB[jq], hi);
        }
    }

    const int sbase = ((dir * BATCH + b) * 4 + quarter) * NPTS;
    #pragma unroll
    for (int jq = 0; jq < QPT; ++jq) {
        const int m = qbase + jq * THREADS;
        g_scratch[sbase + m] = fminf(mnA[jq], mnB[jq]);
    }
}

__global__ __launch_bounds__(THREADS)
void chamfer_stageB(const float* __restrict__ predict,
                    const float* __restrict__ gt,
                    float* __restrict__ out) {
    const int gi  = blockIdx.x * THREADS + threadIdx.x;  // 0..32767
    const int dir = gi >> 14;
    const int rem = gi & 16383;
    const int b   = rem >> 12;
    const int m   = rem & 4095;
    const int tid = threadIdx.x;

    const float* q = (dir == 0) ? predict : gt;
    const int base = b * 3 * NPTS;
    const float px = q[base + 0 * NPTS + m];
    const float py = q[base + 1 * NPTS + m];
    const float pz = q[base + 2 * NPTS + m];
    const float pp = fmaf(px, px, fmaf(py, py, pz * pz));

    const int sbase = ((dir * BATCH + b) * 4) * NPTS + m;
    float s = g_scratch[sbase];
    #pragma unroll
    for (int qt = 1; qt < 4; ++qt)
        s = fminf(s, g_scratch[sbase + qt * NPTS]);

    const float d2  = fmaxf(fmaf(2.0f, s, pp), 0.0f);
    const float val = sqrtf(d2 + 1e-8f) * (1.0f / (float)(BATCH * NPTS));

    __shared__ float red[THREADS];
    red[tid] = val;
    __syncthreads();
    #pragma unroll
    for (int st = THREADS / 2; st >= 32; st >>= 1) {
        if (tid < st) red[tid] += red[tid + st];
        __syncthreads();
    }
    if (tid < 32) {
        float v = red[tid];
        #pragma unroll
        for (int off = 16; off > 0; off >>= 1)
            v += __shfl_down_sync(0xFFFFFFFFu, v, off);
        if (tid == 0) atomicAdd(out, v);
    }
}

extern "C" void kernel_launch(void* const* d_in, const int* in_sizes, int n_in,
                              void* d_out, int out_size) {
    const float* predict = (const float*)d_in[0];
    const float* gt      = (const float*)d_in[1];
    float* out = (float*)d_out;

    chamfer_zero_kernel<<<1, 32>>>(out);

    dim3 gridA(16, 2, BATCH);   // (4 tiles x 4 quarters) x 2 dirs x 4 batch = 128
    chamfer_stageA<<<gridA, THREADS>>>(predict, gt);

    chamfer_stageB<<<128, THREADS>>>(predict, gt, out);
}

// round 5
// speedup vs baseline: 1.6643x; 1.1031x over previous
#include <cuda_runtime.h>
#include <math.h>

// ChamferLoss: predict_pc (4,3,4096), gt_pc (4,3,4096) -> scalar
// min_n ||p-g||^2 = |p|^2 + 2*min_n( h_n - p.g_n ),  h_n = 0.5|g_n|^2
// Stage A: 256 blocks = (4 query tiles x 8 db chunks) x 2 dirs x 4 batch.
//          Block caches 512 db pts (8 KB) -> 2 CTAs/SM, 4 warps/SMSP.
//          4 queries/thread share each shared record; packed f32x2 FFMA.
// Stage B: combine 8 chunk-mins per query, sqrt, mean; block partials +
//          last-block final reduction (no zero kernel, no float atomics).

#define BATCH   4
#define NPTS    4096
#define THREADS 256
#define QPT     4                       // queries per thread
#define NCHUNK  8                       // db chunks
#define DBC     (NPTS / NCHUNK)         // 512 db points per chunk
#define RECS    (DBC / 2)               // 256 interleaved 2-point records
#define QTILE   (THREADS * QPT)         // 1024 queries per tile
#define NTILES  (NPTS / QTILE)          // 4
#define NBLK_B  128                     // stageB blocks (32768 queries / 256)

// scratch[dir][b][chunk][query] : 2*4*8*4096 floats = 1 MB
__device__ float g_scratch[2 * BATCH * NCHUNK * NPTS];
__device__ float g_partials[NBLK_B];
__device__ int   g_count;               // zero-initialized; self-resetting

__device__ __forceinline__ unsigned long long pack2(float lo, float hi) {
    unsigned long long r;
    asm("mov.b64 %0, {%1, %2};" : "=l"(r) : "f"(lo), "f"(hi));
    return r;
}
__device__ __forceinline__ void unpack2(unsigned long long v, float& lo, float& hi) {
    asm("mov.b64 {%0, %1}, %2;" : "=f"(lo), "=f"(hi) : "l"(v));
}
__device__ __forceinline__ unsigned long long fma2(unsigned long long a,
                                                   unsigned long long b,
                                                   unsigned long long c) {
    unsigned long long d;
    asm("fma.rn.f32x2 %0, %1, %2, %3;" : "=l"(d) : "l"(a), "l"(b), "l"(c));
    return d;
}

__global__ __launch_bounds__(THREADS, 2)
void chamfer_stageA(const float* __restrict__ predict,
                    const float* __restrict__ gt) {
    const int tile  = blockIdx.x >> 3;     // 0..3  (query tile of 1024)
    const int chunk = blockIdx.x & 7;      // 0..7  (db chunk of 512)
    const int dir   = blockIdx.y;          // 0: q=predict db=gt ; 1: swapped
    const int b     = blockIdx.z;
    const int tid   = threadIdx.x;

    const float* q  = (dir == 0) ? predict : gt;
    const float* db = (dir == 0) ? gt : predict;
    const int base  = b * 3 * NPTS;

    // Interleaved records: rec[j] = {x0,x1, y0,y1, z0,z1, h0,h1}  (8 KB)
    __shared__ float sdb[DBC * 4];

    for (int k = tid; k < DBC; k += THREADS) {
        const int i  = chunk * DBC + k;
        const float gx = db[base + 0 * NPTS + i];
        const float gy = db[base + 1 * NPTS + i];
        const float gz = db[base + 2 * NPTS + i];
        const float h  = 0.5f * fmaf(gx, gx, fmaf(gy, gy, gz * gz));
        const int j = k >> 1, lane = k & 1;
        sdb[j * 8 + 0 + lane] = gx;
        sdb[j * 8 + 2 + lane] = gy;
        sdb[j * 8 + 4 + lane] = gz;
        sdb[j * 8 + 6 + lane] = h;
    }
    __syncthreads();

    // 4 query points per thread (negated so score = h - p.g via fma)
    unsigned long long qx2[QPT], qy2[QPT], qz2[QPT];
    const int qbase = tile * QTILE + tid;
    #pragma unroll
    for (int jq = 0; jq < QPT; ++jq) {
        const int m = qbase + jq * THREADS;
        const float px = q[base + 0 * NPTS + m];
        const float py = q[base + 1 * NPTS + m];
        const float pz = q[base + 2 * NPTS + m];
        qx2[jq] = pack2(-px, -px);
        qy2[jq] = pack2(-py, -py);
        qz2[jq] = pack2(-pz, -pz);
    }

    float mnA[QPT], mnB[QPT];
    #pragma unroll
    for (int jq = 0; jq < QPT; ++jq) { mnA[jq] = 3.4e38f; mnB[jq] = 3.4e38f; }

    const ulonglong2* s2 = (const ulonglong2*)sdb;
    #pragma unroll 2
    for (int r = 0; r < RECS; ++r) {
        const ulonglong2 A = s2[2 * r + 0];   // {x0,x1},{y0,y1}
        const ulonglong2 B = s2[2 * r + 1];   // {z0,z1},{h0,h1}
        #pragma unroll
        for (int jq = 0; jq < QPT; ++jq) {
            const unsigned long long sc =
                fma2(qx2[jq], A.x, fma2(qy2[jq], A.y, fma2(qz2[jq], B.x, B.y)));
            float lo, hi;
            unpack2(sc, lo, hi);
            mnA[jq] = fminf(mnA[jq], lo);
            mnB[jq] = fminf(mnB[jq], hi);
        }
    }

    const int sbase = ((dir * BATCH + b) * NCHUNK + chunk) * NPTS;
    #pragma unroll
    for (int jq = 0; jq < QPT; ++jq) {
        const int m = qbase + jq * THREADS;
        g_scratch[sbase + m] = fminf(mnA[jq], mnB[jq]);
    }
}

__global__ __launch_bounds__(THREADS)
void chamfer_stageB(const float* __restrict__ predict,
                    const float* __restrict__ gt,
                    float* __restrict__ out) {
    const int gi  = blockIdx.x * THREADS + threadIdx.x;  // 0..32767
    const int dir = gi >> 14;
    const int rem = gi & 16383;
    const int b   = rem >> 12;
    const int m   = rem & 4095;
    const int tid = threadIdx.x;

    const float* q = (dir == 0) ? predict : gt;
    const int base = b * 3 * NPTS;
    const float px = q[base + 0 * NPTS + m];
    const float py = q[base + 1 * NPTS + m];
    const float pz = q[base + 2 * NPTS + m];
    const float pp = fmaf(px, px, fmaf(py, py, pz * pz));

    const int sbase = ((dir * BATCH + b) * NCHUNK) * NPTS + m;
    float s = g_scratch[sbase];
    #pragma unroll
    for (int c = 1; c < NCHUNK; ++c)
        s = fminf(s, g_scratch[sbase + c * NPTS]);

    const float d2  = fmaxf(fmaf(2.0f, s, pp), 0.0f);
    const float val = sqrtf(d2 + 1e-8f) * (1.0f / (float)(BATCH * NPTS));

    // Block reduction -> per-block partial
    __shared__ float red[THREADS];
    red[tid] = val;
    __syncthreads();
    #pragma unroll
    for (int st = THREADS / 2; st >= 32; st >>= 1) {
        if (tid < st) red[tid] += red[tid + st];
        __syncthreads();
    }
    if (tid < 32) {
        float v = red[tid];
        #pragma unroll
        for (int off = 16; off > 0; off >>= 1)
            v += __shfl_down_sync(0xFFFFFFFFu, v, off);
        if (tid == 0) g_partials[blockIdx.x] = v;
    }

    // Last-block-done final reduction (deterministic; resets counter)
    __shared__ int is_last;
    __threadfence();
    if (tid == 0) {
        const int prev = atomicAdd(&g_count, 1);
        is_last = (prev == NBLK_B - 1) ? 1 : 0;
    }
    __syncthreads();
    if (is_last) {
        float v = (tid < NBLK_B) ? g_partials[tid] : 0.0f;
        red[tid] = v;
        __syncthreads();
        if (tid < 64) red[tid] += red[tid + 64];
        __syncthreads();
        if (tid < 32) {
            float w = red[tid] + red[tid + 32];
            #pragma unroll
            for (int off = 16; off > 0; off >>= 1)
                w += __shfl_down_sync(0xFFFFFFFFu, w, off);
            if (tid == 0) {
                out[0]  = w;
                g_count = 0;   // reset for next graph replay
            }
        }
    }
}

extern "C" void kernel_launch(void* const* d_in, const int* in_sizes, int n_in,
                              void* d_out, int out_size) {
    const float* predict = (const float*)d_in[0];
    const float* gt      = (const float*)d_in[1];
    float* out = (float*)d_out;

    dim3 gridA(NTILES * NCHUNK, 2, BATCH);   // 32 x 2 x 4 = 256 blocks
    chamfer_stageA<<<gridA, THREADS>>>(predict, gt);

    chamfer_stageB<<<NBLK_B, THREADS>>>(predict, gt, out);
}